// round 2
// baseline (speedup 1.0000x reference)
#include <cuda_runtime.h>
#include <cuda_bf16.h>
#include <cstdint>

// ============================================================================
// Fused edge-MLP: out[e] = sigmoid(W2 . relu(W1 @ [feats[src[e]]; feats[dst[e]]] + b1) + b2)
// sm_100 (no 'a' features!): mma.sync bf16 HMMA + ldmatrix + cp.async.
// Persistent 148 CTAs; W1 in smem; gathered X tile double-buffered via cp.async;
// fp32 register accumulators; fused fp32 epilogue (layer 2 + sigmoid).
// ============================================================================

#define MAX_NODES 100000
#define HDIM 128
#define KDIM 256
#define TILE_M 128
#define XSTRIDE 528u   // 512 B row + 16 B pad (bank rotation, 16B-aligned)

// bf16 feature table scratch (25.6 MB, L2-resident)
__device__ __nv_bfloat16 g_feats_bf16[(size_t)MAX_NODES * HDIM];

// ---- smem layout ----
#define OFF_BW2  0u                       // float2[128] {b1, w2}
#define OFF_SCR  1024u                    // float[128][2] partial row sums
#define OFF_B2   2048u                    // float b2
#define OFF_W1   2112u                    // 128 x 256 bf16, stride 528
#define W_BYTES  (128u * XSTRIDE)         // 67584
#define OFF_X0   (OFF_W1 + W_BYTES)
#define OFF_X1   (OFF_X0 + W_BYTES)
#define SMEM_DYN (OFF_X1 + W_BYTES)       // 204864 B

// ---------------------------------------------------------------------------
__device__ __forceinline__ uint32_t smem_u32(const void* p) {
    uint32_t a;
    asm("{ .reg .u64 t; cvta.to.shared.u64 t, %1; cvt.u32.u64 %0, t; }" : "=r"(a) : "l"(p));
    return a;
}
__device__ __forceinline__ void cp_async16(uint32_t saddr, const void* gaddr) {
    asm volatile("cp.async.cg.shared.global [%0], [%1], 16;"
                 :: "r"(saddr), "l"(gaddr) : "memory");
}
__device__ __forceinline__ void cp_commit() {
    asm volatile("cp.async.commit_group;" ::: "memory");
}
template <int N>
__device__ __forceinline__ void cp_wait() {
    asm volatile("cp.async.wait_group %0;" :: "n"(N) : "memory");
}
__device__ __forceinline__ void ldsm_x4(uint32_t* r, uint32_t addr) {
    asm volatile("ldmatrix.sync.aligned.m8n8.x4.shared.b16 {%0,%1,%2,%3}, [%4];"
                 : "=r"(r[0]), "=r"(r[1]), "=r"(r[2]), "=r"(r[3]) : "r"(addr));
}
__device__ __forceinline__ void mma_bf16(float* c, const uint32_t* a,
                                         uint32_t b0, uint32_t b1) {
    asm volatile(
        "mma.sync.aligned.m16n8k16.row.col.f32.bf16.bf16.f32 "
        "{%0,%1,%2,%3}, {%4,%5,%6,%7}, {%8,%9}, {%0,%1,%2,%3};"
        : "+f"(c[0]), "+f"(c[1]), "+f"(c[2]), "+f"(c[3])
        : "r"(a[0]), "r"(a[1]), "r"(a[2]), "r"(a[3]), "r"(b0), "r"(b1));
}

// Gather one tile of 128 edges into smem X tile (rows: [src feats | dst feats]).
__device__ __forceinline__ void gather_tile(uint32_t sb, uint32_t xoff,
                                            const int* __restrict__ src,
                                            const int* __restrict__ dst,
                                            int tile_base, int E) {
    int tid = threadIdx.x;
    int c = tid & 15;         // 16B chunk within a 256B node row
    int rh0 = tid >> 4;       // 0..15
#pragma unroll
    for (int p = 0; p < 16; p++) {
        int rh = p * 16 + rh0;        // row-half 0..255
        int m = rh >> 1, half = rh & 1;
        int e = tile_base + m;
        if (e >= E) e = E - 1;
        int node = half ? __ldg(dst + e) : __ldg(src + e);
        const char* gp = (const char*)(g_feats_bf16 + (size_t)node * HDIM) + c * 16;
        uint32_t sp = sb + xoff + (uint32_t)m * XSTRIDE + (uint32_t)half * 256u + (uint32_t)c * 16u;
        cp_async16(sp, gp);
    }
}

// ---------------------------------------------------------------------------
__global__ void convert_feats_kernel(const float* __restrict__ f, int n) {
    int i = (blockIdx.x * blockDim.x + threadIdx.x) * 4;
    if (i < n) {
        float4 v = *(const float4*)(f + i);
        __nv_bfloat162* o = (__nv_bfloat162*)(g_feats_bf16 + i);
        o[0] = __floats2bfloat162_rn(v.x, v.y);
        o[1] = __floats2bfloat162_rn(v.z, v.w);
    }
}

// ---------------------------------------------------------------------------
__global__ __launch_bounds__(256, 1) void edge_mlp_kernel(
    const int* __restrict__ src, const int* __restrict__ dst,
    const float* __restrict__ W1, const float* __restrict__ b1,
    const float* __restrict__ W2, const float* __restrict__ b2,
    float* __restrict__ out, int E)
{
    extern __shared__ char sm[];
    uint32_t sb = smem_u32(sm);
    int tid = threadIdx.x, wid = tid >> 5, lid = tid & 31;

    // ---- one-time setup: constants + W1 -> bf16 smem ----
    if (tid == 0) *(float*)(sm + OFF_B2) = b2[0];
    if (tid < 128)
        ((float2*)(sm + OFF_BW2))[tid] = make_float2(b1[tid], W2[tid]);
    for (int i = tid; i < 128 * 128; i += 256) {
        int n = i >> 7;
        int c0 = (i & 127) * 2;                 // even k col
        float2 w = *(const float2*)(W1 + n * KDIM + c0);
        *(__nv_bfloat162*)(sm + OFF_W1 + (uint32_t)n * XSTRIDE + (uint32_t)c0 * 2u) =
            __floats2bfloat162_rn(w.x, w.y);
    }
    __syncthreads();

    int ntiles = (E + TILE_M - 1) / TILE_M;
    int bx = blockIdx.x, g = gridDim.x;
    int nmy = (bx < ntiles) ? ((ntiles - bx - 1) / g + 1) : 0;
    const uint32_t xoff[2] = {OFF_X0, OFF_X1};

    // warp tiling: 4 (M) x 2 (N); warp tile m32 x n64, K=256
    int mbase = (wid & 3) * 32;
    int nbase = (wid >> 2) * 64;
    // lane-constant smem offsets (classic ldmatrix addressing)
    uint32_t a_lane = (uint32_t)((mbase + (lid & 15)) * XSTRIDE + ((lid >> 4) * 8) * 2);
    uint32_t b_lane = sb + OFF_W1 +
        (uint32_t)((nbase + (lid & 7) + ((lid >> 4) << 3)) * XSTRIDE +
                   (((lid >> 3) & 1) * 8) * 2);

    if (nmy > 0) {
        gather_tile(sb, OFF_X0, src, dst, bx * TILE_M, E);
        cp_commit();
    }

    for (int j = 0; j < nmy; j++) {
        int cur = j & 1, nxt = cur ^ 1;
        int tile_base = (bx + j * g) * TILE_M;

        if (j + 1 < nmy) {
            gather_tile(sb, xoff[nxt], src, dst, (bx + (j + 1) * g) * TILE_M, E);
            cp_commit();
            cp_wait<1>();
        } else {
            cp_wait<0>();
        }
        __syncthreads();   // X(cur) visible to all warps

        // ---- GEMM: H = X @ W1^T on tile (cur) ----
        float acc[2][8][4];
#pragma unroll
        for (int mt = 0; mt < 2; mt++)
#pragma unroll
            for (int nt = 0; nt < 8; nt++)
#pragma unroll
                for (int q = 0; q < 4; q++) acc[mt][nt][q] = 0.f;

        uint32_t abase = sb + xoff[cur] + a_lane;
#pragma unroll
        for (int ks = 0; ks < 16; ks++) {
            uint32_t koff = (uint32_t)ks * 32u;   // k0*2 bytes
            uint32_t a[2][4], b[4][4];
#pragma unroll
            for (int mt = 0; mt < 2; mt++)
                ldsm_x4(a[mt], abase + koff + (uint32_t)mt * (16u * XSTRIDE));
#pragma unroll
            for (int bt = 0; bt < 4; bt++)
                ldsm_x4(b[bt], b_lane + koff + (uint32_t)bt * (16u * XSTRIDE));
#pragma unroll
            for (int mt = 0; mt < 2; mt++)
#pragma unroll
                for (int nt = 0; nt < 8; nt++) {
                    int bt = nt >> 1, hi = (nt & 1) << 1;
                    mma_bf16(acc[mt][nt], a[mt], b[bt][hi], b[bt][hi + 1]);
                }
        }

        // ---- epilogue: relu(h + b1) . w2, warp-level reduce ----
        {
            const float2* bw2 = (const float2*)(sm + OFF_BW2);
            float s[2][2] = {{0.f, 0.f}, {0.f, 0.f}};
#pragma unroll
            for (int mt = 0; mt < 2; mt++)
#pragma unroll
                for (int nt = 0; nt < 8; nt++) {
                    int col0 = nbase + nt * 8 + 2 * (lid & 3);
                    float2 ba = bw2[col0], bb = bw2[col0 + 1];
                    const float* c = acc[mt][nt];
                    s[mt][0] += fmaxf(c[0] + ba.x, 0.f) * ba.y +
                                fmaxf(c[1] + bb.x, 0.f) * bb.y;
                    s[mt][1] += fmaxf(c[2] + ba.x, 0.f) * ba.y +
                                fmaxf(c[3] + bb.x, 0.f) * bb.y;
                }
#pragma unroll
            for (int d = 1; d <= 2; d <<= 1) {
#pragma unroll
                for (int mt = 0; mt < 2; mt++) {
                    s[mt][0] += __shfl_xor_sync(0xFFFFFFFF, s[mt][0], d);
                    s[mt][1] += __shfl_xor_sync(0xFFFFFFFF, s[mt][1], d);
                }
            }
            if ((lid & 3) == 0) {
                int jc = wid >> 2;
                float* scr = (float*)(sm + OFF_SCR);
#pragma unroll
                for (int mt = 0; mt < 2; mt++) {
                    int r = mbase + mt * 16 + (lid >> 2);
                    scr[r * 2 + jc] = s[mt][0];
                    scr[(r + 8) * 2 + jc] = s[mt][1];
                }
            }
        }
        __syncthreads();

        if (tid < 128) {
            int e = tile_base + tid;
            if (e < E) {
                const float* scr = (const float*)(sm + OFF_SCR);
                float v = scr[tid * 2] + scr[tid * 2 + 1] + *(const float*)(sm + OFF_B2);
                out[e] = 1.f / (1.f + __expf(-v));
            }
        }
        __syncthreads();   // scr + X(cur) free for reuse
    }
}

// ---------------------------------------------------------------------------
extern "C" void kernel_launch(void* const* d_in, const int* in_sizes, int n_in,
                              void* d_out, int out_size) {
    const int*   src   = (const int*)d_in[0];
    const int*   dst   = (const int*)d_in[1];
    const float* feats = (const float*)d_in[2];
    const float* W1    = (const float*)d_in[3];
    const float* b1    = (const float*)d_in[4];
    const float* W2    = (const float*)d_in[5];
    const float* b2    = (const float*)d_in[6];
    float* out = (float*)d_out;
    int E = in_sizes[0];
    int nfeat = in_sizes[2];   // n_nodes * 128

    int vecn = nfeat / 4;
    convert_feats_kernel<<<(vecn + 255) / 256, 256>>>(feats, nfeat);

    cudaFuncSetAttribute(edge_mlp_kernel,
                         cudaFuncAttributeMaxDynamicSharedMemorySize, SMEM_DYN);
    edge_mlp_kernel<<<148, 256, SMEM_DYN>>>(src, dst, W1, b1, W2, b2, out, E);
}

// round 3
// speedup vs baseline: 1.0253x; 1.0253x over previous
#include <cuda_runtime.h>
#include <cuda_bf16.h>
#include <cstdint>

// ============================================================================
// Fused edge-MLP: out[e] = sigmoid(W2 . relu(W1 @ [feats[src[e]]; feats[dst[e]]] + b1) + b2)
// sm_100 plain target: mma.sync bf16 + ldmatrix + cp.async.
// R3: 512 threads (16 warps, m32n32 warp tiles), software-pipelined ldsm frags.
// ============================================================================

#define MAX_NODES 100000
#define HDIM 128
#define KDIM 256
#define TILE_M 128
#define XSTRIDE 528u   // 512 B row + 16 B pad

__device__ __nv_bfloat16 g_feats_bf16[(size_t)MAX_NODES * HDIM];

// ---- smem layout ----
#define OFF_BW2  0u                       // float2[128] {b1, w2}
#define OFF_SCR  1024u                    // float[128][4] partial row sums
#define OFF_B2   3072u                    // float b2
#define OFF_W1   3136u                    // 128 x 256 bf16, stride 528
#define W_BYTES  (128u * XSTRIDE)         // 67584
#define OFF_X0   (OFF_W1 + W_BYTES)
#define OFF_X1   (OFF_X0 + W_BYTES)
#define SMEM_DYN (OFF_X1 + W_BYTES)

// ---------------------------------------------------------------------------
__device__ __forceinline__ uint32_t smem_u32(const void* p) {
    uint32_t a;
    asm("{ .reg .u64 t; cvta.to.shared.u64 t, %1; cvt.u32.u64 %0, t; }" : "=r"(a) : "l"(p));
    return a;
}
__device__ __forceinline__ void cp_async16(uint32_t saddr, const void* gaddr) {
    asm volatile("cp.async.cg.shared.global [%0], [%1], 16;"
                 :: "r"(saddr), "l"(gaddr) : "memory");
}
__device__ __forceinline__ void cp_commit() {
    asm volatile("cp.async.commit_group;" ::: "memory");
}
template <int N>
__device__ __forceinline__ void cp_wait() {
    asm volatile("cp.async.wait_group %0;" :: "n"(N) : "memory");
}
__device__ __forceinline__ void ldsm_x4(uint32_t* r, uint32_t addr) {
    asm volatile("ldmatrix.sync.aligned.m8n8.x4.shared.b16 {%0,%1,%2,%3}, [%4];"
                 : "=r"(r[0]), "=r"(r[1]), "=r"(r[2]), "=r"(r[3]) : "r"(addr));
}
__device__ __forceinline__ void mma_bf16(float* c, const uint32_t* a,
                                         uint32_t b0, uint32_t b1) {
    asm volatile(
        "mma.sync.aligned.m16n8k16.row.col.f32.bf16.bf16.f32 "
        "{%0,%1,%2,%3}, {%4,%5,%6,%7}, {%8,%9}, {%0,%1,%2,%3};"
        : "+f"(c[0]), "+f"(c[1]), "+f"(c[2]), "+f"(c[3])
        : "r"(a[0]), "r"(a[1]), "r"(a[2]), "r"(a[3]), "r"(b0), "r"(b1));
}

// Gather one tile of 128 edges into smem X tile. 512 threads: 8 cp.async each.
__device__ __forceinline__ void gather_tile(uint32_t sb, uint32_t xoff,
                                            const int* __restrict__ src,
                                            const int* __restrict__ dst,
                                            int tile_base, int E) {
    int tid = threadIdx.x;
    int c = tid & 15;          // 16B chunk within 256B node row
    int rh0 = tid >> 4;        // 0..31
#pragma unroll
    for (int p = 0; p < 8; p++) {
        int rh = p * 32 + rh0;         // row-half 0..255
        int m = rh >> 1, half = rh & 1;
        int e = tile_base + m;
        if (e >= E) e = E - 1;
        int node = half ? __ldg(dst + e) : __ldg(src + e);
        const char* gp = (const char*)(g_feats_bf16 + (size_t)node * HDIM) + c * 16;
        uint32_t sp = sb + xoff + (uint32_t)m * XSTRIDE + (uint32_t)half * 256u + (uint32_t)c * 16u;
        cp_async16(sp, gp);
    }
}

// ---------------------------------------------------------------------------
__global__ void convert_feats_kernel(const float* __restrict__ f, int n) {
    int i = (blockIdx.x * blockDim.x + threadIdx.x) * 4;
    if (i < n) {
        float4 v = *(const float4*)(f + i);
        __nv_bfloat162* o = (__nv_bfloat162*)(g_feats_bf16 + i);
        o[0] = __floats2bfloat162_rn(v.x, v.y);
        o[1] = __floats2bfloat162_rn(v.z, v.w);
    }
}

// ---------------------------------------------------------------------------
__global__ __launch_bounds__(512, 1) void edge_mlp_kernel(
    const int* __restrict__ src, const int* __restrict__ dst,
    const float* __restrict__ W1, const float* __restrict__ b1,
    const float* __restrict__ W2, const float* __restrict__ b2,
    float* __restrict__ out, int E)
{
    extern __shared__ char sm[];
    uint32_t sb = smem_u32(sm);
    int tid = threadIdx.x, wid = tid >> 5, lid = tid & 31;

    // ---- one-time setup ----
    if (tid == 0) *(float*)(sm + OFF_B2) = b2[0];
    if (tid < 128)
        ((float2*)(sm + OFF_BW2))[tid] = make_float2(b1[tid], W2[tid]);
    for (int i = tid; i < 128 * 128; i += 512) {
        int n = i >> 7;
        int c0 = (i & 127) * 2;
        float2 w = *(const float2*)(W1 + n * KDIM + c0);
        *(__nv_bfloat162*)(sm + OFF_W1 + (uint32_t)n * XSTRIDE + (uint32_t)c0 * 2u) =
            __floats2bfloat162_rn(w.x, w.y);
    }
    __syncthreads();

    int ntiles = (E + TILE_M - 1) / TILE_M;
    int bx = blockIdx.x, g = gridDim.x;
    int nmy = (bx < ntiles) ? ((ntiles - bx - 1) / g + 1) : 0;
    const uint32_t xoff[2] = {OFF_X0, OFF_X1};

    // warp grid 4 (M) x 4 (N); warp tile m32 x n32, K=256
    int mw = wid & 3, nw = wid >> 2;
    int mbase = mw * 32, nbase = nw * 32;
    uint32_t a_lane = (uint32_t)((mbase + (lid & 15)) * XSTRIDE + ((lid >> 4) * 8) * 2);
    uint32_t b_lane = sb + OFF_W1 +
        (uint32_t)((nbase + (lid & 7) + ((lid >> 4) << 3)) * XSTRIDE +
                   (((lid >> 3) & 1) * 8) * 2);

    if (nmy > 0) {
        gather_tile(sb, OFF_X0, src, dst, bx * TILE_M, E);
        cp_commit();
    }

    for (int j = 0; j < nmy; j++) {
        int cur = j & 1, nxt = cur ^ 1;
        int tile_base = (bx + j * g) * TILE_M;

        if (j + 1 < nmy) {
            gather_tile(sb, xoff[nxt], src, dst, (bx + (j + 1) * g) * TILE_M, E);
            cp_commit();
            cp_wait<1>();
        } else {
            cp_wait<0>();
        }
        __syncthreads();   // X(cur) visible

        // ---- GEMM: H = X @ W1^T (software-pipelined fragments) ----
        float acc[2][4][4];
#pragma unroll
        for (int mt = 0; mt < 2; mt++)
#pragma unroll
            for (int nt = 0; nt < 4; nt++)
#pragma unroll
                for (int q = 0; q < 4; q++) acc[mt][nt][q] = 0.f;

        uint32_t abase = sb + xoff[cur] + a_lane;
        uint32_t a[2][2][4], b[2][2][4];   // [buf][tile][frag]

        // prologue: load ks=0 into buf 0
#pragma unroll
        for (int t = 0; t < 2; t++) {
            ldsm_x4(a[0][t], abase + (uint32_t)t * (16u * XSTRIDE));
            ldsm_x4(b[0][t], b_lane + (uint32_t)t * (16u * XSTRIDE));
        }

#pragma unroll
        for (int ks = 0; ks < 16; ks++) {
            int cb = ks & 1, nb = cb ^ 1;
            if (ks < 15) {
                uint32_t koff = (uint32_t)(ks + 1) * 32u;
#pragma unroll
                for (int t = 0; t < 2; t++) {
                    ldsm_x4(a[nb][t], abase + koff + (uint32_t)t * (16u * XSTRIDE));
                    ldsm_x4(b[nb][t], b_lane + koff + (uint32_t)t * (16u * XSTRIDE));
                }
            }
#pragma unroll
            for (int mt = 0; mt < 2; mt++)
#pragma unroll
                for (int nt = 0; nt < 4; nt++) {
                    int bt = nt >> 1, hi = (nt & 1) << 1;
                    mma_bf16(acc[mt][nt], a[cb][mt], b[cb][bt][hi], b[cb][bt][hi + 1]);
                }
        }

        // ---- epilogue: relu(h + b1) . w2, quad reduce, smem partials ----
        {
            const float2* bw2 = (const float2*)(sm + OFF_BW2);
            float s[2][2] = {{0.f, 0.f}, {0.f, 0.f}};
#pragma unroll
            for (int mt = 0; mt < 2; mt++)
#pragma unroll
                for (int nt = 0; nt < 4; nt++) {
                    int col0 = nbase + nt * 8 + 2 * (lid & 3);
                    float2 ba = bw2[col0], bb = bw2[col0 + 1];
                    const float* c = acc[mt][nt];
                    s[mt][0] += fmaxf(c[0] + ba.x, 0.f) * ba.y +
                                fmaxf(c[1] + bb.x, 0.f) * bb.y;
                    s[mt][1] += fmaxf(c[2] + ba.x, 0.f) * ba.y +
                                fmaxf(c[3] + bb.x, 0.f) * bb.y;
                }
#pragma unroll
            for (int d = 1; d <= 2; d <<= 1) {
#pragma unroll
                for (int mt = 0; mt < 2; mt++) {
                    s[mt][0] += __shfl_xor_sync(0xFFFFFFFF, s[mt][0], d);
                    s[mt][1] += __shfl_xor_sync(0xFFFFFFFF, s[mt][1], d);
                }
            }
            if ((lid & 3) == 0) {
                float* scr = (float*)(sm + OFF_SCR);
#pragma unroll
                for (int mt = 0; mt < 2; mt++) {
                    int r = mbase + mt * 16 + (lid >> 2);
                    scr[r * 4 + nw] = s[mt][0];
                    scr[(r + 8) * 4 + nw] = s[mt][1];
                }
            }
        }
        __syncthreads();

        if (tid < 128) {
            int e = tile_base + tid;
            if (e < E) {
                const float4 p = ((const float4*)(sm + OFF_SCR))[tid];
                float v = p.x + p.y + p.z + p.w + *(const float*)(sm + OFF_B2);
                out[e] = 1.f / (1.f + __expf(-v));
            }
        }
        __syncthreads();
    }
}

// ---------------------------------------------------------------------------
extern "C" void kernel_launch(void* const* d_in, const int* in_sizes, int n_in,
                              void* d_out, int out_size) {
    const int*   src   = (const int*)d_in[0];
    const int*   dst   = (const int*)d_in[1];
    const float* feats = (const float*)d_in[2];
    const float* W1    = (const float*)d_in[3];
    const float* b1    = (const float*)d_in[4];
    const float* W2    = (const float*)d_in[5];
    const float* b2    = (const float*)d_in[6];
    float* out = (float*)d_out;
    int E = in_sizes[0];
    int nfeat = in_sizes[2];

    int vecn = nfeat / 4;
    convert_feats_kernel<<<(vecn + 255) / 256, 256>>>(feats, nfeat);

    cudaFuncSetAttribute(edge_mlp_kernel,
                         cudaFuncAttributeMaxDynamicSharedMemorySize, SMEM_DYN);
    edge_mlp_kernel<<<148, 512, SMEM_DYN>>>(src, dst, W1, b1, W2, b2, out, E);
}